// round 3
// baseline (speedup 1.0000x reference)
#include <cuda_runtime.h>
#include <cuda_bf16.h>

#define WARPS_PER_BLOCK 8
#define NT 32
#define MC 4
#define NITER_MAX 64
#define LOG2E 1.4426950408889634f

// One warp per batch element. Lane i owns row i of HH (32 regs) and the
// 4-element state Gn = -G*log2e. Per-iteration xt broadcast goes through a
// double-buffered 32-float shared row read back as LDS.128 broadcasts.
__global__ void __launch_bounds__(WARPS_PER_BLOCK * 32, 1)
cmdnet_kernel(const float* __restrict__ yt,
              const float* __restrict__ Ht,
              const float* __restrict__ sigmat0,
              const float* __restrict__ m_c,
              const float* __restrict__ alpha,
              const float* __restrict__ taui,
              const float* __restrict__ delta,
              float* __restrict__ out,
              int B, int NR, int NITER)
{
    __shared__ __align__(16) float4 s_lasc[NITER_MAX];  // la_j * scale_it * log2e
    __shared__ __align__(16) float4 s_misc[NITER_MAX];  // {-scale_raw, -ta, d*log2e, 0}
    __shared__ float s_la[MC];                           // log(alpha_j)
    __shared__ float s_tauN, s_tauNl2;                   // |taui[N]|, |taui[N]|*log2e
    __shared__ __align__(16) float s_stage[2][WARPS_PER_BLOCK][8][NT];
    __shared__ __align__(16) float s_xt[2][WARPS_PER_BLOCK][NT];

    const int tid   = threadIdx.x;
    const int wslot = tid >> 5;
    const int lane  = tid & 31;

    if (tid < NITER) {
        float ta = fabsf(taui[tid]);
        float scale_raw = (tid == 0) ? 1.0f : ta;     // first_iter softmax scale = 1
        float sc = scale_raw * LOG2E;
        float4 l;
        l.x = logf(alpha[0]) * sc;
        l.y = logf(alpha[1]) * sc;
        l.z = logf(alpha[2]) * sc;
        l.w = logf(alpha[3]) * sc;
        s_lasc[tid] = l;
        float4 ms;
        ms.x = -scale_raw;
        ms.y = -ta;
        ms.z = delta[tid] * LOG2E;
        ms.w = 0.0f;
        s_misc[tid] = ms;
    }
    if (tid < MC) s_la[tid] = logf(alpha[tid]);
    if (tid == 0) {
        float tn = fabsf(taui[NITER]);
        s_tauN   = tn;
        s_tauNl2 = tn * LOG2E;
    }
    __syncthreads();

    const int b = blockIdx.x * WARPS_PER_BLOCK + wslot;
    if (b >= B) return;

    const float* Hb = Ht + (size_t)b * NR * NT;
    const float* yb = yt + (size_t)b * NR;

    // ---------------- Phase 1: HH row (per lane) + yH ----------------
    float hh[NT];
    #pragma unroll
    for (int k = 0; k < NT; k++) hh[k] = 0.0f;
    float yH = 0.0f;

    #pragma unroll
    for (int g = 0; g < 8; g++) {            // NR = 64 -> 8 groups of 8 rows
        const int r0 = g * 8;
        const int buf = g & 1;
        float h[8];
        #pragma unroll
        for (int rr = 0; rr < 8; rr++) {
            h[rr] = Hb[(r0 + rr) * NT + lane];           // coalesced 128B/row
            s_stage[buf][wslot][rr][lane] = h[rr];
            yH = fmaf(yb[r0 + rr], h[rr], yH);           // broadcast LDG
        }
        __syncwarp();   // RAW fence; WAR on alt buffer covered by next group's sync
        #pragma unroll
        for (int rr = 0; rr < 8; rr++) {
            #pragma unroll
            for (int kk = 0; kk < 8; kk++) {
                float4 v = *reinterpret_cast<const float4*>(&s_stage[buf][wslot][rr][4 * kk]);
                hh[4 * kk + 0] = fmaf(h[rr], v.x, hh[4 * kk + 0]);
                hh[4 * kk + 1] = fmaf(h[rr], v.y, hh[4 * kk + 1]);
                hh[4 * kk + 2] = fmaf(h[rr], v.z, hh[4 * kk + 2]);
                hh[4 * kk + 3] = fmaf(h[rr], v.w, hh[4 * kk + 3]);
            }
        }
    }

    // ---------------- Phase 2: 64 iterations ----------------
    float mj[MC];
    #pragma unroll
    for (int j = 0; j < MC; j++) mj[j] = m_c[j];

    float Gn[MC] = {0.0f, 0.0f, 0.0f, 0.0f};   // Gn = -G * log2e
    float sig2, nsig2;
    { float s = sigmat0[b]; sig2 = s * s; nsig2 = -sig2; }

    float e[MC];
    float inv = 0.0f, xt = 0.0f;

    for (int it = 0; it < NITER; it++) {
        const float4 lasc = s_lasc[it];
        const float4 msc  = s_misc[it];   // {-scale_raw, -ta, d*log2e}
        const int buf = it & 1;

        // z_j (log2 domain) = la_j*sc + G_j*sc = lasc_j - Gn_j*scale_raw
        float z[MC];
        z[0] = fmaf(msc.x, Gn[0], lasc.x);
        z[1] = fmaf(msc.x, Gn[1], lasc.y);
        z[2] = fmaf(msc.x, Gn[2], lasc.z);
        z[3] = fmaf(msc.x, Gn[3], lasc.w);
        float mx = fmaxf(fmaxf(z[0], z[1]), fmaxf(z[2], z[3]));
        #pragma unroll
        for (int j = 0; j < MC; j++) e[j] = exp2f(z[j] - mx);
        float sum = (e[0] + e[1]) + (e[2] + e[3]);
        inv = __fdividef(1.0f, sum);

        // soft symbol: xt = (sum_j e_j m_j) * inv
        float em = e[0] * mj[0];
        #pragma unroll
        for (int j = 1; j < MC; j++) em = fmaf(e[j], mj[j], em);
        xt = em * inv;

        // broadcast xt across the warp (double-buffered), then xHH dot
        s_xt[buf][wslot][lane] = xt;
        __syncwarp();
        float acc = 0.0f;
        #pragma unroll
        for (int kk = 0; kk < 8; kk++) {
            float4 v = *reinterpret_cast<const float4*>(&s_xt[buf][wslot][4 * kk]);
            acc = fmaf(v.x, hh[4 * kk + 0], acc);
            acc = fmaf(v.y, hh[4 * kk + 1], acc);
            acc = fmaf(v.z, hh[4 * kk + 2], acc);
            acc = fmaf(v.w, hh[4 * kk + 3], acc);
        }

        // grad_L_j = sig2*(1-exp(-G_j)) + ta*(xHH-yH) * f_j*(m_j - xt)
        //          = t_j + ci * (e_j*(m_j - xt)),  ci = ta*(xHH-yH)*inv
        const float c  = (yH - acc) * msc.y;     // = ta*(acc - yH)
        const float ci = c * inv;
        #pragma unroll
        for (int j = 0; j < MC; j++) {
            float eg = exp2f(Gn[j]);             // exp(-G_j)
            float t  = fmaf(nsig2, eg, sig2);    // sig2*(1-eg)
            float w  = e[j] * (mj[j] - xt);
            float gl = fmaf(ci, w, t);
            Gn[j] = fmaf(msc.z, gl, Gn[j]);      // Gn += d*log2e*gl
        }
    }

    // ---------------- Final layer: softmax + soft symbol ----------------
    float f[MC];
    {
        const float tl2 = s_tauNl2, tn = s_tauN;
        float z[MC];
        #pragma unroll
        for (int j = 0; j < MC; j++) z[j] = fmaf(-tn, Gn[j], s_la[j] * tl2);
        float mx = fmaxf(fmaxf(z[0], z[1]), fmaxf(z[2], z[3]));
        #pragma unroll
        for (int j = 0; j < MC; j++) e[j] = exp2f(z[j] - mx);
        float sum = (e[0] + e[1]) + (e[2] + e[3]);
        float iv = __fdividef(1.0f, sum);
        #pragma unroll
        for (int j = 0; j < MC; j++) f[j] = e[j] * iv;
        float em = f[0] * mj[0];
        #pragma unroll
        for (int j = 1; j < MC; j++) em = fmaf(f[j], mj[j], em);
        xt = em;
    }

    // ---------------- Write out: ft [B,NT,MC] then xt [B,NT] ----------------
    const size_t base = (size_t)b * NT + lane;
    float4 o;
    o.x = f[0]; o.y = f[1]; o.z = f[2]; o.w = f[3];
    *reinterpret_cast<float4*>(&out[base * MC]) = o;     // coalesced 16B stores
    out[(size_t)B * NT * MC + base] = xt;
}

extern "C" void kernel_launch(void* const* d_in, const int* in_sizes, int n_in,
                              void* d_out, int out_size)
{
    const float* yt     = (const float*)d_in[0];
    const float* Ht     = (const float*)d_in[1];
    const float* sig    = (const float*)d_in[2];
    const float* m      = (const float*)d_in[3];
    const float* alpha  = (const float*)d_in[4];
    const float* taui   = (const float*)d_in[5];
    const float* delta  = (const float*)d_in[6];

    const int B     = in_sizes[2];
    const int NR    = in_sizes[0] / B;
    const int NITER = in_sizes[6];

    const int blocks = (B + WARPS_PER_BLOCK - 1) / WARPS_PER_BLOCK;
    cmdnet_kernel<<<blocks, WARPS_PER_BLOCK * 32>>>(
        yt, Ht, sig, m, alpha, taui, delta, (float*)d_out, B, NR, NITER);
}

// round 4
// speedup vs baseline: 1.3284x; 1.3284x over previous
#include <cuda_runtime.h>
#include <cuda_bf16.h>

#define WARPS_PER_BLOCK 8
#define NT 32
#define MC 4
#define NITER_MAX 64
#define LOG2E 1.4426950408889634f

// One warp per batch element. Lane i owns row i of HH (32 regs) and the
// 4-element state Gn = -G*log2e. Per-iteration xt broadcast goes through a
// double-buffered 32-float shared row read back as LDS.128 broadcasts.
__global__ void __launch_bounds__(WARPS_PER_BLOCK * 32, 2)
cmdnet_kernel(const float* __restrict__ yt,
              const float* __restrict__ Ht,
              const float* __restrict__ sigmat0,
              const float* __restrict__ m_c,
              const float* __restrict__ alpha,
              const float* __restrict__ taui,
              const float* __restrict__ delta,
              float* __restrict__ out,
              int B, int NR, int NITER)
{
    __shared__ __align__(16) float4 s_lasc[NITER_MAX];  // la_j * scale_it * log2e
    __shared__ __align__(16) float4 s_misc[NITER_MAX];  // {-scale_raw, -ta, d*log2e, 0}
    __shared__ float s_la[MC];                           // log(alpha_j)
    __shared__ float s_tauN, s_tauNl2;                   // |taui[N]|, |taui[N]|*log2e
    __shared__ __align__(16) float s_stage[WARPS_PER_BLOCK][8][NT];
    __shared__ __align__(16) float s_xt[2][WARPS_PER_BLOCK][NT];

    const int tid   = threadIdx.x;
    const int wslot = tid >> 5;
    const int lane  = tid & 31;

    if (tid < NITER) {
        float ta = fabsf(taui[tid]);
        float scale_raw = (tid == 0) ? 1.0f : ta;     // first_iter softmax scale = 1
        float sc = scale_raw * LOG2E;
        float4 l;
        l.x = logf(alpha[0]) * sc;
        l.y = logf(alpha[1]) * sc;
        l.z = logf(alpha[2]) * sc;
        l.w = logf(alpha[3]) * sc;
        s_lasc[tid] = l;
        float4 ms;
        ms.x = -scale_raw;
        ms.y = -ta;
        ms.z = delta[tid] * LOG2E;
        ms.w = 0.0f;
        s_misc[tid] = ms;
    }
    if (tid < MC) s_la[tid] = logf(alpha[tid]);
    if (tid == 0) {
        float tn = fabsf(taui[NITER]);
        s_tauN   = tn;
        s_tauNl2 = tn * LOG2E;
    }
    __syncthreads();

    const int b = blockIdx.x * WARPS_PER_BLOCK + wslot;
    if (b >= B) return;

    const float* Hb = Ht + (size_t)b * NR * NT;
    const float* yb = yt + (size_t)b * NR;

    // ---------------- Phase 1: HH row (per lane) + yH ----------------
    float hh[NT];
    #pragma unroll
    for (int k = 0; k < NT; k++) hh[k] = 0.0f;
    float yH = 0.0f;

    for (int r0 = 0; r0 < NR; r0 += 8) {       // runtime loop: keeps regs lean
        float h[8];
        #pragma unroll
        for (int rr = 0; rr < 8; rr++) {
            h[rr] = Hb[(r0 + rr) * NT + lane];           // coalesced 128B/row
            s_stage[wslot][rr][lane] = h[rr];
            yH = fmaf(yb[r0 + rr], h[rr], yH);           // broadcast LDG
        }
        __syncwarp();
        #pragma unroll
        for (int rr = 0; rr < 8; rr++) {
            #pragma unroll
            for (int kk = 0; kk < 8; kk++) {
                float4 v = *reinterpret_cast<const float4*>(&s_stage[wslot][rr][4 * kk]);
                hh[4 * kk + 0] = fmaf(h[rr], v.x, hh[4 * kk + 0]);
                hh[4 * kk + 1] = fmaf(h[rr], v.y, hh[4 * kk + 1]);
                hh[4 * kk + 2] = fmaf(h[rr], v.z, hh[4 * kk + 2]);
                hh[4 * kk + 3] = fmaf(h[rr], v.w, hh[4 * kk + 3]);
            }
        }
        __syncwarp();
    }

    // ---------------- Phase 2: 64 iterations ----------------
    float mj[MC];
    #pragma unroll
    for (int j = 0; j < MC; j++) mj[j] = m_c[j];

    float Gn[MC] = {0.0f, 0.0f, 0.0f, 0.0f};   // Gn = -G * log2e
    float sig2, nsig2;
    { float s = sigmat0[b]; sig2 = s * s; nsig2 = -sig2; }

    float e[MC];
    float inv = 0.0f, xt = 0.0f;

    for (int it = 0; it < NITER; it++) {
        const float4 lasc = s_lasc[it];
        const float4 msc  = s_misc[it];   // {-scale_raw, -ta, d*log2e}
        const int buf = it & 1;

        // z_j (log2 domain) = (la_j + G_j)*scale*log2e = lasc_j - Gn_j*scale_raw
        float z[MC];
        z[0] = fmaf(msc.x, Gn[0], lasc.x);
        z[1] = fmaf(msc.x, Gn[1], lasc.y);
        z[2] = fmaf(msc.x, Gn[2], lasc.z);
        z[3] = fmaf(msc.x, Gn[3], lasc.w);
        float mx = fmaxf(fmaxf(z[0], z[1]), fmaxf(z[2], z[3]));
        #pragma unroll
        for (int j = 0; j < MC; j++) e[j] = exp2f(z[j] - mx);
        float sum = (e[0] + e[1]) + (e[2] + e[3]);
        inv = __fdividef(1.0f, sum);

        // soft symbol: xt = (sum_j e_j m_j) * inv
        float em = e[0] * mj[0];
        #pragma unroll
        for (int j = 1; j < MC; j++) em = fmaf(e[j], mj[j], em);
        xt = em * inv;

        // broadcast xt across the warp (double-buffered -> one syncwarp), xHH dot
        s_xt[buf][wslot][lane] = xt;
        __syncwarp();
        float acc = 0.0f;
        #pragma unroll
        for (int kk = 0; kk < 8; kk++) {
            float4 v = *reinterpret_cast<const float4*>(&s_xt[buf][wslot][4 * kk]);
            acc = fmaf(v.x, hh[4 * kk + 0], acc);
            acc = fmaf(v.y, hh[4 * kk + 1], acc);
            acc = fmaf(v.z, hh[4 * kk + 2], acc);
            acc = fmaf(v.w, hh[4 * kk + 3], acc);
        }

        // grad_L_j = sig2*(1-exp(-G_j)) + ta*(xHH-yH)*inv * e_j*(m_j - xt)
        const float c  = (yH - acc) * msc.y;     // = ta*(acc - yH)
        const float ci = c * inv;
        #pragma unroll
        for (int j = 0; j < MC; j++) {
            float eg = exp2f(Gn[j]);             // exp(-G_j)
            float t  = fmaf(nsig2, eg, sig2);    // sig2*(1-eg)
            float w  = e[j] * (mj[j] - xt);
            float gl = fmaf(ci, w, t);
            Gn[j] = fmaf(msc.z, gl, Gn[j]);      // Gn += d*log2e*gl
        }
    }

    // ---------------- Final layer: softmax + soft symbol ----------------
    float f[MC];
    {
        const float tl2 = s_tauNl2, tn = s_tauN;
        float z[MC];
        #pragma unroll
        for (int j = 0; j < MC; j++) z[j] = fmaf(-tn, Gn[j], s_la[j] * tl2);
        float mx = fmaxf(fmaxf(z[0], z[1]), fmaxf(z[2], z[3]));
        #pragma unroll
        for (int j = 0; j < MC; j++) e[j] = exp2f(z[j] - mx);
        float sum = (e[0] + e[1]) + (e[2] + e[3]);
        float iv = __fdividef(1.0f, sum);
        #pragma unroll
        for (int j = 0; j < MC; j++) f[j] = e[j] * iv;
        float em = f[0] * mj[0];
        #pragma unroll
        for (int j = 1; j < MC; j++) em = fmaf(f[j], mj[j], em);
        xt = em;
    }

    // ---------------- Write out: ft [B,NT,MC] then xt [B,NT] ----------------
    const size_t base = (size_t)b * NT + lane;
    float4 o;
    o.x = f[0]; o.y = f[1]; o.z = f[2]; o.w = f[3];
    *reinterpret_cast<float4*>(&out[base * MC]) = o;     // coalesced 16B stores
    out[(size_t)B * NT * MC + base] = xt;
}

extern "C" void kernel_launch(void* const* d_in, const int* in_sizes, int n_in,
                              void* d_out, int out_size)
{
    const float* yt     = (const float*)d_in[0];
    const float* Ht     = (const float*)d_in[1];
    const float* sig    = (const float*)d_in[2];
    const float* m      = (const float*)d_in[3];
    const float* alpha  = (const float*)d_in[4];
    const float* taui   = (const float*)d_in[5];
    const float* delta  = (const float*)d_in[6];

    const int B     = in_sizes[2];
    const int NR    = in_sizes[0] / B;
    const int NITER = in_sizes[6];

    const int blocks = (B + WARPS_PER_BLOCK - 1) / WARPS_PER_BLOCK;
    cmdnet_kernel<<<blocks, WARPS_PER_BLOCK * 32>>>(
        yt, Ht, sig, m, alpha, taui, delta, (float*)d_out, B, NR, NITER);
}

// round 5
// speedup vs baseline: 1.3612x; 1.0247x over previous
#include <cuda_runtime.h>
#include <cuda_bf16.h>

#define WARPS_PER_BLOCK 8
#define NT 32
#define MC 4
#define NITER_MAX 64
#define LOG2E 1.4426950408889634f

union f2u { float2 f; unsigned long long u; };

static __device__ __forceinline__ float2 fma2(float2 a, float2 b, float2 c) {
    f2u A, Bv, C, D; A.f = a; Bv.f = b; C.f = c;
    asm("fma.rn.f32x2 %0, %1, %2, %3;" : "=l"(D.u) : "l"(A.u), "l"(Bv.u), "l"(C.u));
    return D.f;
}
static __device__ __forceinline__ float2 mul2(float2 a, float2 b) {
    f2u A, Bv, D; A.f = a; Bv.f = b;
    asm("mul.rn.f32x2 %0, %1, %2;" : "=l"(D.u) : "l"(A.u), "l"(Bv.u));
    return D.f;
}
static __device__ __forceinline__ float2 add2(float2 a, float2 b) {
    f2u A, Bv, D; A.f = a; Bv.f = b;
    asm("add.rn.f32x2 %0, %1, %2;" : "=l"(D.u) : "l"(A.u), "l"(Bv.u));
    return D.f;
}
static __device__ __forceinline__ float rcp_fast(float x) {
    float r; asm("rcp.approx.f32 %0, %1;" : "=f"(r) : "f"(x)); return r;
}

// One warp per batch element. Lane i owns row i of HH as 16 float2 regs and
// the 4-element state Gn = -G*log2e as 2 float2. Heavy FMA blocks use
// Blackwell packed fma.rn.f32x2 (one issue slot per 2 fp32 FMAs).
__global__ void __launch_bounds__(WARPS_PER_BLOCK * 32, 2)
cmdnet_kernel(const float* __restrict__ yt,
              const float* __restrict__ Ht,
              const float* __restrict__ sigmat0,
              const float* __restrict__ m_c,
              const float* __restrict__ alpha,
              const float* __restrict__ taui,
              const float* __restrict__ delta,
              float* __restrict__ out,
              int B, int NR, int NITER)
{
    __shared__ __align__(16) float4 s_lasc[NITER_MAX];  // la_j * scale_it * log2e
    __shared__ __align__(16) float4 s_p1[NITER_MAX];    // {-sc, -sc, -ta, d*log2e}
    __shared__ float s_la[MC];                           // log(alpha_j)
    __shared__ float s_tauN, s_tauNl2;                   // |taui[N]|, |taui[N]|*log2e
    __shared__ __align__(16) float s_stage[WARPS_PER_BLOCK][8][NT];
    __shared__ __align__(16) float s_xt[2][WARPS_PER_BLOCK][NT];

    const int tid   = threadIdx.x;
    const int wslot = tid >> 5;
    const int lane  = tid & 31;

    if (tid < NITER) {
        float ta = fabsf(taui[tid]);
        float scale_raw = (tid == 0) ? 1.0f : ta;     // first_iter softmax scale = 1
        float sc = scale_raw * LOG2E;
        float4 l;
        l.x = logf(alpha[0]) * sc;
        l.y = logf(alpha[1]) * sc;
        l.z = logf(alpha[2]) * sc;
        l.w = logf(alpha[3]) * sc;
        s_lasc[tid] = l;
        float4 p;
        p.x = -scale_raw;
        p.y = -scale_raw;
        p.z = -ta;
        p.w = delta[tid] * LOG2E;
        s_p1[tid] = p;
    }
    if (tid < MC) s_la[tid] = logf(alpha[tid]);
    if (tid == 0) {
        float tn = fabsf(taui[NITER]);
        s_tauN   = tn;
        s_tauNl2 = tn * LOG2E;
    }
    __syncthreads();

    const int b = blockIdx.x * WARPS_PER_BLOCK + wslot;
    if (b >= B) return;

    const float* Hb = Ht + (size_t)b * NR * NT;
    const float* yb = yt + (size_t)b * NR;

    // ---------------- Phase 1: HH row (per lane, packed f32x2) + yH ----------
    float2 hh2[NT / 2];
    #pragma unroll
    for (int k = 0; k < NT / 2; k++) hh2[k] = make_float2(0.0f, 0.0f);
    float yH = 0.0f;

    for (int r0 = 0; r0 < NR; r0 += 8) {       // runtime loop: keeps regs lean
        float h[8];
        #pragma unroll
        for (int rr = 0; rr < 8; rr++) {
            h[rr] = Hb[(r0 + rr) * NT + lane];           // coalesced 128B/row
            s_stage[wslot][rr][lane] = h[rr];
            yH = fmaf(yb[r0 + rr], h[rr], yH);           // broadcast LDG
        }
        __syncwarp();
        #pragma unroll
        for (int rr = 0; rr < 8; rr++) {
            const float2 h2 = make_float2(h[rr], h[rr]);
            #pragma unroll
            for (int kk = 0; kk < 8; kk++) {
                float4 v = *reinterpret_cast<const float4*>(&s_stage[wslot][rr][4 * kk]);
                hh2[2 * kk + 0] = fma2(h2, make_float2(v.x, v.y), hh2[2 * kk + 0]);
                hh2[2 * kk + 1] = fma2(h2, make_float2(v.z, v.w), hh2[2 * kk + 1]);
            }
        }
        __syncwarp();
    }

    // ---------------- Phase 2: 64 iterations ----------------
    float2 m2[2];
    m2[0] = make_float2(m_c[0], m_c[1]);
    m2[1] = make_float2(m_c[2], m_c[3]);

    float2 Gn2[2] = {make_float2(0.f, 0.f), make_float2(0.f, 0.f)}; // -G*log2e
    float2 sig2_2, nsig2_2;
    { float s = sigmat0[b]; float s2 = s * s;
      sig2_2 = make_float2(s2, s2); nsig2_2 = make_float2(-s2, -s2); }

    float e0, e1, e2, e3;
    float inv = 0.0f, xt = 0.0f;

    for (int it = 0; it < NITER; it++) {
        const float4 lasc = s_lasc[it];
        const float4 p    = s_p1[it];     // {-sc, -sc, -ta, d*log2e}
        const float2 sc2  = make_float2(p.x, p.y);
        const int buf = it & 1;

        // z (log2 domain) = lasc - Gn*scale  (packed)
        float2 z0 = fma2(sc2, Gn2[0], make_float2(lasc.x, lasc.y));
        float2 z1 = fma2(sc2, Gn2[1], make_float2(lasc.z, lasc.w));
        float mx = fmaxf(fmaxf(z0.x, z0.y), fmaxf(z1.x, z1.y));
        e0 = exp2f(z0.x - mx); e1 = exp2f(z0.y - mx);
        e2 = exp2f(z1.x - mx); e3 = exp2f(z1.y - mx);
        float sum = (e0 + e1) + (e2 + e3);
        inv = rcp_fast(sum);

        // soft symbol: xt = (sum_j e_j m_j) * inv
        float em = e0 * m2[0].x;
        em = fmaf(e1, m2[0].y, em);
        em = fmaf(e2, m2[1].x, em);
        em = fmaf(e3, m2[1].y, em);
        xt = em * inv;

        // broadcast xt across the warp (double-buffered), packed xHH dot
        s_xt[buf][wslot][lane] = xt;
        __syncwarp();
        float2 acc0 = make_float2(0.f, 0.f), acc1 = make_float2(0.f, 0.f);
        #pragma unroll
        for (int kk = 0; kk < 8; kk++) {
            float4 v = *reinterpret_cast<const float4*>(&s_xt[buf][wslot][4 * kk]);
            acc0 = fma2(make_float2(v.x, v.y), hh2[2 * kk + 0], acc0);
            acc1 = fma2(make_float2(v.z, v.w), hh2[2 * kk + 1], acc1);
        }
        float acc = (acc0.x + acc0.y) + (acc1.x + acc1.y);

        // grad_L_j = sig2*(1-exp(-G_j)) + ci * e_j*(m_j - xt),  ci = ta*(xHH-yH)*inv
        const float c  = (yH - acc) * p.z;       // = ta*(acc - yH)
        const float ci = c * inv;
        const float2 ci2  = make_float2(ci, ci);
        const float2 dl2  = make_float2(p.w, p.w);
        const float2 nxt2 = make_float2(-xt, -xt);
        const float2 eg0 = make_float2(exp2f(Gn2[0].x), exp2f(Gn2[0].y)); // exp(-G)
        const float2 eg1 = make_float2(exp2f(Gn2[1].x), exp2f(Gn2[1].y));
        float2 t0 = fma2(nsig2_2, eg0, sig2_2);  // sig2*(1-eg)
        float2 t1 = fma2(nsig2_2, eg1, sig2_2);
        float2 d0 = add2(m2[0], nxt2);           // m - xt
        float2 d1 = add2(m2[1], nxt2);
        float2 w0 = mul2(make_float2(e0, e1), d0);
        float2 w1 = mul2(make_float2(e2, e3), d1);
        float2 g0 = fma2(ci2, w0, t0);
        float2 g1 = fma2(ci2, w1, t1);
        Gn2[0] = fma2(dl2, g0, Gn2[0]);          // Gn += d*log2e*gl
        Gn2[1] = fma2(dl2, g1, Gn2[1]);
    }

    // ---------------- Final layer: softmax + soft symbol ----------------
    float f[MC];
    {
        const float tl2 = s_tauNl2, tn = s_tauN;
        const float2 ntn2 = make_float2(-tn, -tn);
        float2 z0 = fma2(ntn2, Gn2[0], make_float2(s_la[0] * tl2, s_la[1] * tl2));
        float2 z1 = fma2(ntn2, Gn2[1], make_float2(s_la[2] * tl2, s_la[3] * tl2));
        float mx = fmaxf(fmaxf(z0.x, z0.y), fmaxf(z1.x, z1.y));
        e0 = exp2f(z0.x - mx); e1 = exp2f(z0.y - mx);
        e2 = exp2f(z1.x - mx); e3 = exp2f(z1.y - mx);
        float sum = (e0 + e1) + (e2 + e3);
        float iv = __fdividef(1.0f, sum);
        f[0] = e0 * iv; f[1] = e1 * iv; f[2] = e2 * iv; f[3] = e3 * iv;
        float em = f[0] * m2[0].x;
        em = fmaf(f[1], m2[0].y, em);
        em = fmaf(f[2], m2[1].x, em);
        em = fmaf(f[3], m2[1].y, em);
        xt = em;
    }

    // ---------------- Write out: ft [B,NT,MC] then xt [B,NT] ----------------
    const size_t base = (size_t)b * NT + lane;
    float4 o;
    o.x = f[0]; o.y = f[1]; o.z = f[2]; o.w = f[3];
    *reinterpret_cast<float4*>(&out[base * MC]) = o;     // coalesced 16B stores
    out[(size_t)B * NT * MC + base] = xt;
}

extern "C" void kernel_launch(void* const* d_in, const int* in_sizes, int n_in,
                              void* d_out, int out_size)
{
    const float* yt     = (const float*)d_in[0];
    const float* Ht     = (const float*)d_in[1];
    const float* sig    = (const float*)d_in[2];
    const float* m      = (const float*)d_in[3];
    const float* alpha  = (const float*)d_in[4];
    const float* taui   = (const float*)d_in[5];
    const float* delta  = (const float*)d_in[6];

    const int B     = in_sizes[2];
    const int NR    = in_sizes[0] / B;
    const int NITER = in_sizes[6];

    const int blocks = (B + WARPS_PER_BLOCK - 1) / WARPS_PER_BLOCK;
    cmdnet_kernel<<<blocks, WARPS_PER_BLOCK * 32>>>(
        yt, Ht, sig, m, alpha, taui, delta, (float*)d_out, B, NR, NITER);
}